// round 2
// baseline (speedup 1.0000x reference)
#include <cuda_runtime.h>
#include <cuda_bf16.h>
#include <cstdint>

// Problem dims
#define TSEQ 2048
#define HU   200
#define NG   800           // 4*HU gates
#define VOC  50257
#define VBLK 786           // ceil(VOC/64)

// ---------------- device scratch (static globals; no runtime allocation) ----
__device__ __align__(16) float4 g_xg0[TSEQ * HU];   // enc L0: x@Wx + b, per (t, unit) i/j/f/o
__device__ float g_henc[HU];                        // encoder final h (layer 0)
__device__ float g_h1T[HU * TSEQ];                  // decoder top outputs, transposed [k][t]
__device__ float g_part[TSEQ * VBLK];               // per-(t, vblock) partial sum of exp
__device__ float g_losst[TSEQ];                     // per-t NLL

// ---------------- helpers ----------------
__device__ __forceinline__ float sigf(float x) {
    return __fdividef(1.0f, 1.0f + __expf(-x));
}
__device__ __forceinline__ float tanh_fast(float x) {
    float xc = fminf(fmaxf(x, -15.0f), 15.0f);
    float e  = __expf(2.0f * xc);
    return __fdividef(e - 1.0f, e + 1.0f);
}
__device__ __forceinline__ uint32_t ctarank() {
    uint32_t r;
    asm("mov.u32 %0, %%cluster_ctarank;" : "=r"(r));
    return r;
}
__device__ __forceinline__ void cluster_sync_() {
    asm volatile("barrier.cluster.arrive.aligned;" ::: "memory");
    asm volatile("barrier.cluster.wait.aligned;"   ::: "memory");
}
// store float to the same smem offset in cluster CTA r
__device__ __forceinline__ void st_cluster_f32(float* local_addr, int r, float v) {
    uint32_t a = (uint32_t)__cvta_generic_to_shared(local_addr);
    asm volatile(
        "{ .reg .b32 ra; mapa.shared::cluster.u32 ra, %0, %1; "
        "st.shared::cluster.f32 [ra], %2; }"
        :: "r"(a), "r"(r), "f"(v) : "memory");
}

// ================= kernel 1: embedding lookup + encoder L0 input gates ======
// g_xg0[t][u] = (i,j,f,o) input-half gate pre-activations incl. bias
__global__ __launch_bounds__(256) void xg0_kernel(
    const int* __restrict__ sent, const float* __restrict__ emb,
    const float* __restrict__ W0, const float* __restrict__ b0)
{
    __shared__ float xs[4][HU];
    int t0 = blockIdx.x * 4;
    int tid = threadIdx.x;
    for (int i = tid; i < 4 * HU; i += 256) {
        int tt = i / HU, k = i % HU;
        xs[tt][k] = emb[(long)sent[t0 + tt] * HU + k];
    }
    __syncthreads();
    if (tid < HU) {
        int u = tid;
        float4 acc[4];
        float4 bias = make_float4(b0[u], b0[HU + u], b0[2 * HU + u], b0[3 * HU + u]);
        #pragma unroll
        for (int tt = 0; tt < 4; tt++) acc[tt] = bias;
        for (int k = 0; k < HU; k++) {
            const float* row = W0 + (long)k * NG;
            float wi = row[u], wj = row[HU + u], wf = row[2 * HU + u], wo = row[3 * HU + u];
            #pragma unroll
            for (int tt = 0; tt < 4; tt++) {
                float x = xs[tt][k];
                acc[tt].x += wi * x; acc[tt].y += wj * x;
                acc[tt].z += wf * x; acc[tt].w += wo * x;
            }
        }
        #pragma unroll
        for (int tt = 0; tt < 4; tt++) g_xg0[(t0 + tt) * HU + u] = acc[tt];
    }
}

// ================= kernel 2: encoder L0 recurrence (cluster of 8) ===========
// 8 CTAs x 256 thr. CTA owns 25 h-units. Warp w: k-slice [25w, 25w+25).
// Recurrent weights register-resident (100 floats/thread).
__global__ __launch_bounds__(256, 1) __cluster_dims__(8, 1, 1)
void enc_kernel(const float* __restrict__ W0)
{
    __shared__ float  h_s[2][HU];
    __shared__ float4 part_s[8][25];
    int tid = threadIdx.x, w = tid >> 5, u = tid & 31;
    uint32_t rank = ctarank();
    int ug = rank * 25 + u;

    float wr[25][4];
    if (u < 25) {
        #pragma unroll
        for (int kk = 0; kk < 25; kk++) {
            const float* row = W0 + (long)(HU + w * 25 + kk) * NG;
            wr[kk][0] = row[ug];
            wr[kk][1] = row[HU + ug];
            wr[kk][2] = row[2 * HU + ug];
            wr[kk][3] = row[3 * HU + ug];
        }
    }
    for (int i = tid; i < HU; i += 256) { h_s[0][i] = 0.f; h_s[1][i] = 0.f; }
    float c0 = 0.f;
    __syncthreads();
    cluster_sync_();

    int cur = 0;
    for (int t = 0; t < TSEQ; t++) {
        float4 xg;
        if (w == 0 && u < 25) xg = __ldg(&g_xg0[t * HU + ug]);  // overlaps partials
        if (u < 25) {
            float4 a = make_float4(0.f, 0.f, 0.f, 0.f);
            #pragma unroll
            for (int kk = 0; kk < 25; kk++) {
                float hk = h_s[cur][w * 25 + kk];
                a.x += wr[kk][0] * hk; a.y += wr[kk][1] * hk;
                a.z += wr[kk][2] * hk; a.w += wr[kk][3] * hk;
            }
            part_s[w][u] = a;
        }
        __syncthreads();
        if (w == 0 && u < 25) {
            float4 s = xg;
            #pragma unroll
            for (int p = 0; p < 8; p++) {
                float4 q = part_s[p][u];
                s.x += q.x; s.y += q.y; s.z += q.z; s.w += q.w;
            }
            c0 = c0 * sigf(s.z + 1.0f) + sigf(s.x) * tanh_fast(s.y);
            float h = tanh_fast(c0) * sigf(s.w);
            #pragma unroll
            for (int r = 0; r < 8; r++) st_cluster_f32(&h_s[1 - cur][ug], r, h);
        }
        cluster_sync_();
        cur ^= 1;
    }
    if (rank == 0)
        for (int i = tid; i < HU; i += 256) g_henc[i] = h_s[cur][i];
}

// ================= kernel 3: decoder 2-layer recurrence (cluster of 8) ======
// Pipelined: super-step s computes L0 step s and L1 step s-1 (one sync/step).
// L0 recurrent weights in registers; L1 full weights (400x800) in SMEM fp32.
#define DEC_SMEM 170400
__global__ __launch_bounds__(256, 1) __cluster_dims__(8, 1, 1)
void dec_kernel(const float* __restrict__ W0d, const float* __restrict__ b0d,
                const float* __restrict__ W1d, const float* __restrict__ b1d)
{
    extern __shared__ float4 sm4[];
    float4* w1q  = sm4;            // [400*25]
    float4* pL0  = w1q + 10000;    // [8*25]
    float4* pL1  = pL0 + 200;      // [8*25]
    float4* xin0 = pL1 + 200;      // [25]
    float4* b1q  = xin0 + 25;      // [25]
    float*  h0s  = (float*)(b1q + 25);  // [2][200]
    float*  h1s  = h0s + 2 * HU;        // [2][200]

    int tid = threadIdx.x, w = tid >> 5, u = tid & 31;
    uint32_t rank = ctarank();
    int ug = rank * 25 + u;

    // L0 recurrent weights -> registers
    float wr0[25][4];
    if (u < 25) {
        #pragma unroll
        for (int kk = 0; kk < 25; kk++) {
            const float* row = W0d + (long)(HU + w * 25 + kk) * NG;
            wr0[kk][0] = row[ug];
            wr0[kk][1] = row[HU + ug];
            wr0[kk][2] = row[2 * HU + ug];
            wr0[kk][3] = row[3 * HU + ug];
        }
    }
    // L1 weights -> SMEM
    if (u < 25) {
        for (int kk = 0; kk < 50; kk++) {
            int k = w * 50 + kk;
            const float* row = W1d + (long)k * NG;
            w1q[k * 25 + u] = make_float4(row[ug], row[HU + ug],
                                          row[2 * HU + ug], row[3 * HU + ug]);
        }
    }
    // stage henc in pL1 region; zero state buffers
    float* st_h = (float*)pL1;
    for (int i = tid; i < HU; i += 256) st_h[i] = g_henc[i];
    for (int i = tid; i < 2 * HU; i += 256) { h0s[i] = 0.f; h1s[i] = 0.f; }
    __syncthreads();
    // xin0 = henc @ W0d[0:200] + b0 (constant decoder input contribution)
    if (u < 25) {
        float4 a = make_float4(0.f, 0.f, 0.f, 0.f);
        for (int kk = 0; kk < 25; kk++) {
            int k = w * 25 + kk;
            const float* row = W0d + (long)k * NG;
            float x = st_h[k];
            a.x += row[ug] * x;          a.y += row[HU + ug] * x;
            a.z += row[2 * HU + ug] * x; a.w += row[3 * HU + ug] * x;
        }
        pL0[w * 25 + u] = a;
    }
    __syncthreads();
    if (w == 0 && u < 25) {
        float4 s = make_float4(b0d[ug], b0d[HU + ug], b0d[2 * HU + ug], b0d[3 * HU + ug]);
        #pragma unroll
        for (int p = 0; p < 8; p++) {
            float4 q = pL0[p * 25 + u];
            s.x += q.x; s.y += q.y; s.z += q.z; s.w += q.w;
        }
        xin0[u] = s;
    }
    if (w == 1 && u < 25)
        b1q[u] = make_float4(b1d[ug], b1d[HU + ug], b1d[2 * HU + ug], b1d[3 * HU + ug]);
    __syncthreads();
    cluster_sync_();

    int cur = 0;
    float c0 = 0.f, c1 = 0.f;
    for (int s = 0; s <= TSEQ; s++) {
        if (u < 25) {
            if (s < TSEQ) {  // L0 partials (register weights)
                float4 a = make_float4(0.f, 0.f, 0.f, 0.f);
                #pragma unroll
                for (int kk = 0; kk < 25; kk++) {
                    float hk = h0s[cur * HU + w * 25 + kk];
                    a.x += wr0[kk][0] * hk; a.y += wr0[kk][1] * hk;
                    a.z += wr0[kk][2] * hk; a.w += wr0[kk][3] * hk;
                }
                pL0[w * 25 + u] = a;
            }
            if (s >= 1) {    // L1 partials (smem weights); input = [h0[s-1], h1[s-2]]
                float4 a = make_float4(0.f, 0.f, 0.f, 0.f);
                const float* inbuf = (w < 4) ? (h0s + cur * HU) : (h1s + cur * HU - HU);
                #pragma unroll
                for (int kk2 = 0; kk2 < 25; kk2++) {
                    int k = w * 50 + 2 * kk2;
                    float2 xk = *(const float2*)&inbuf[k];
                    float4 wa = w1q[k * 25 + u];
                    float4 wb = w1q[(k + 1) * 25 + u];
                    a.x += wa.x * xk.x + wb.x * xk.y;
                    a.y += wa.y * xk.x + wb.y * xk.y;
                    a.z += wa.z * xk.x + wb.z * xk.y;
                    a.w += wa.w * xk.x + wb.w * xk.y;
                }
                pL1[w * 25 + u] = a;
            }
        }
        __syncthreads();
        if (w == 0 && u < 25 && s < TSEQ) {
            float4 sm = xin0[u];
            #pragma unroll
            for (int p = 0; p < 8; p++) {
                float4 q = pL0[p * 25 + u];
                sm.x += q.x; sm.y += q.y; sm.z += q.z; sm.w += q.w;
            }
            c0 = c0 * sigf(sm.z + 1.0f) + sigf(sm.x) * tanh_fast(sm.y);
            float h = tanh_fast(c0) * sigf(sm.w);
            #pragma unroll
            for (int r = 0; r < 8; r++) st_cluster_f32(&h0s[(1 - cur) * HU + ug], r, h);
        }
        if (w == 1 && u < 25 && s >= 1) {
            float4 sm = b1q[u];
            #pragma unroll
            for (int p = 0; p < 8; p++) {
                float4 q = pL1[p * 25 + u];
                sm.x += q.x; sm.y += q.y; sm.z += q.z; sm.w += q.w;
            }
            c1 = c1 * sigf(sm.z + 1.0f) + sigf(sm.x) * tanh_fast(sm.y);
            float h = tanh_fast(c1) * sigf(sm.w);
            #pragma unroll
            for (int r = 0; r < 8; r++) st_cluster_f32(&h1s[(1 - cur) * HU + ug], r, h);
            g_h1T[ug * TSEQ + (s - 1)] = h;   // transposed store for loss kernel
        }
        cluster_sync_();
        cur ^= 1;
    }
}

// ================= kernel 4: fused logits + partial sumexp ==================
// 64t x 64v tile per block, 256 threads, 4x4 register tile per thread.
__global__ __launch_bounds__(256) void loss_kernel(
    const float* __restrict__ wmat, const float* __restrict__ bvec)
{
    __shared__ float hs[40][64];
    __shared__ float ws[40][64];
    int tid = threadIdx.x;
    int tx = tid & 15, ty = tid >> 4;
    int v0 = blockIdx.x * 64, t0 = blockIdx.y * 64;
    float acc[4][4] = {};

    for (int ch = 0; ch < 5; ch++) {
        int kb = ch * 40;
        #pragma unroll
        for (int i = 0; i < 10; i++) {
            int idx = tid + 256 * i;
            int kk = idx >> 6, col = idx & 63;
            hs[kk][col] = g_h1T[(kb + kk) * TSEQ + t0 + col];
            int v = v0 + col;
            ws[kk][col] = (v < VOC) ? wmat[(long)(kb + kk) * VOC + v] : 0.f;
        }
        __syncthreads();
        #pragma unroll 8
        for (int kk = 0; kk < 40; kk++) {
            float4 hv = *(const float4*)&hs[kk][ty * 4];
            float4 wv = *(const float4*)&ws[kk][tx * 4];
            acc[0][0] += hv.x * wv.x; acc[0][1] += hv.x * wv.y;
            acc[0][2] += hv.x * wv.z; acc[0][3] += hv.x * wv.w;
            acc[1][0] += hv.y * wv.x; acc[1][1] += hv.y * wv.y;
            acc[1][2] += hv.y * wv.z; acc[1][3] += hv.y * wv.w;
            acc[2][0] += hv.z * wv.x; acc[2][1] += hv.z * wv.y;
            acc[2][2] += hv.z * wv.z; acc[2][3] += hv.z * wv.w;
            acc[3][0] += hv.w * wv.x; acc[3][1] += hv.w * wv.y;
            acc[3][2] += hv.w * wv.z; acc[3][3] += hv.w * wv.w;
        }
        __syncthreads();
    }
    float bv[4];
    #pragma unroll
    for (int j = 0; j < 4; j++) {
        int v = v0 + tx * 4 + j;
        bv[j] = (v < VOC) ? bvec[v] : -1e30f;
    }
    #pragma unroll
    for (int i = 0; i < 4; i++) {
        float e = 0.f;
        #pragma unroll
        for (int j = 0; j < 4; j++) e += __expf(acc[i][j] + bv[j]);
        #pragma unroll
        for (int m = 8; m >= 1; m >>= 1) e += __shfl_xor_sync(0xffffffffu, e, m, 32);
        if (tx == 0) g_part[(t0 + ty * 4 + i) * VBLK + blockIdx.x] = e;  // deterministic
    }
}

// ================= kernel 5: per-t NLL (sumexp reduce + target logit) =======
__global__ __launch_bounds__(256) void finalize_kernel(
    const int* __restrict__ sent, const float* __restrict__ wmat,
    const float* __restrict__ bvec)
{
    int tid = threadIdx.x, lane = tid & 31;
    int t = blockIdx.x * 8 + (tid >> 5);
    float s = 0.f;
    for (int j = lane; j < VBLK; j += 32) s += g_part[t * VBLK + j];
    int tgt = sent[t];
    float d = 0.f;
    for (int k = lane; k < HU; k += 32)
        d += g_h1T[k * TSEQ + t] * wmat[(long)k * VOC + tgt];
    #pragma unroll
    for (int m = 16; m >= 1; m >>= 1) {
        s += __shfl_xor_sync(0xffffffffu, s, m);
        d += __shfl_xor_sync(0xffffffffu, d, m);
    }
    if (lane == 0) g_losst[t] = __logf(s) - (d + bvec[tgt]);
}

// ================= kernel 6: deterministic total sum ========================
__global__ __launch_bounds__(256) void sumloss_kernel(float* out)
{
    __shared__ float red[256];
    int tid = threadIdx.x;
    float s = 0.f;
    #pragma unroll
    for (int i = 0; i < 8; i++) s += g_losst[tid * 8 + i];
    red[tid] = s;
    __syncthreads();
    for (int m = 128; m >= 1; m >>= 1) {
        if (tid < m) red[tid] += red[tid + m];
        __syncthreads();
    }
    if (tid == 0) out[0] = red[0];
}

// ================= launch ===================================================
extern "C" void kernel_launch(void* const* d_in, const int* in_sizes, int n_in,
                              void* d_out, int out_size)
{
    const int*   sent  = (const int*)  d_in[0];
    const float* emb   = (const float*)d_in[1];
    const float* encW0 = (const float*)d_in[2];
    const float* encb0 = (const float*)d_in[3];
    // d_in[4], d_in[5]: enc layer 1 — provably unused by the reference output
    const float* decW0 = (const float*)d_in[6];
    const float* decb0 = (const float*)d_in[7];
    const float* decW1 = (const float*)d_in[8];
    const float* decb1 = (const float*)d_in[9];
    const float* smw   = (const float*)d_in[10];
    const float* smb   = (const float*)d_in[11];
    float* out = (float*)d_out;

    cudaFuncSetAttribute(dec_kernel, cudaFuncAttributeMaxDynamicSharedMemorySize, DEC_SMEM);

    xg0_kernel<<<TSEQ / 4, 256>>>(sent, emb, encW0, encb0);
    enc_kernel<<<8, 256>>>(encW0);
    dec_kernel<<<8, 256, DEC_SMEM>>>(decW0, decb0, decW1, decb1);
    loss_kernel<<<dim3(VBLK, TSEQ / 64), 256>>>(smw, smb);
    finalize_kernel<<<TSEQ / 8, 256>>>(sent, smw, smb);
    sumloss_kernel<<<1, 256>>>(out);
}